// round 7
// baseline (speedup 1.0000x reference)
#include <cuda_runtime.h>
#include <cstdint>
#include <math.h>

#define B_ 32
#define C_ 64
#define M_ 9216
#define KSPLIT 18
#define KPC (M_ / KSPLIT)      // 512 k per CTA
#define KCH 32                 // k-chunk width (floats)
#define NCHK (KPC / KCH)       // 16 chunks
#define NPAIR (NCHK / 2)       // 8 pair-iterations
#define SMS 36                 // smem row stride (floats), pad 4

typedef unsigned long long ull;

// Scratch (no allocs allowed)
__device__ __align__(16) float g_gram_part[KSPLIT * B_ * C_ * C_];
__device__ __align__(16) float g_sum_part[KSPLIT * B_ * C_];
__device__ float g_gate[B_ * C_];

__device__ __forceinline__ uint32_t cvt_tf32(float v) {
    uint32_t r; asm("cvt.rna.tf32.f32 %0, %1;" : "=r"(r) : "f"(v)); return r;
}
__device__ __forceinline__ void mma_tf32(float (&d)[4], const uint32_t a[4], const uint32_t b[2]) {
    asm volatile(
        "mma.sync.aligned.m16n8k8.row.col.f32.tf32.tf32.f32 "
        "{%0,%1,%2,%3}, {%4,%5,%6,%7}, {%8,%9}, {%0,%1,%2,%3};"
        : "+f"(d[0]), "+f"(d[1]), "+f"(d[2]), "+f"(d[3])
        : "r"(a[0]), "r"(a[1]), "r"(a[2]), "r"(a[3]), "r"(b[0]), "r"(b[1]));
}

__device__ __forceinline__ void stage_chunk(uint32_t* dst, float4 v0, float4 v1,
                                            int lrow, int lj, float& cs0, float& cs1) {
    cs0 += v0.x + v0.y + v0.z + v0.w;
    cs1 += v1.x + v1.y + v1.z + v1.w;
    uint4 h0, h1;
    h0.x = cvt_tf32(v0.x); h0.y = cvt_tf32(v0.y); h0.z = cvt_tf32(v0.z); h0.w = cvt_tf32(v0.w);
    h1.x = cvt_tf32(v1.x); h1.y = cvt_tf32(v1.y); h1.z = cvt_tf32(v1.z); h1.w = cvt_tf32(v1.w);
    *reinterpret_cast<uint4*>(dst + lrow * SMS + 4 * lj) = h0;
    *reinterpret_cast<uint4*>(dst + (lrow + 32) * SMS + 4 * lj) = h1;
}

// ---------------------------------------------------------------------------
// Kernel 1: tensor-core Gram, tf32 single-pass.
// 256 threads, 8 warps. Pairwise pipeline: warps 0-3 consume even chunks,
// warps 4-7 odd chunks; one barrier per two chunks. Each warp: 32x32 tile.
// launch_bounds(256,4): cap regs at 64 for 4 CTAs/SM.
// ---------------------------------------------------------------------------
__global__ void __launch_bounds__(256, 4) gram_tc(const float* __restrict__ x) {
    __shared__ __align__(16) uint32_t s_stage[4][64 * SMS];  // 36 KB

    const int ks = blockIdx.x, bi = blockIdx.y;
    const int tid = threadIdx.x;
    const int w = tid >> 5, l = tid & 31;
    const int lq = l >> 2, lr = l & 3;
    const int qd = w >> 2, wq = w & 3;            // qd: which chunk of the pair
    const int rbase = (wq >> 1) << 5, cbase = (wq & 1) << 5;

    const int lrow = tid >> 3;       // 0..31
    const int lj = tid & 7;          // float4 index within 32-float chunk

    const float* xb = x + ((size_t)bi * C_) * M_ + (size_t)ks * KPC + 4 * lj;
    const float* p0 = xb + (size_t)lrow * M_;
    const float* p1 = xb + (size_t)(lrow + 32) * M_;

    float acc[2][4][4];
#pragma unroll
    for (int mg = 0; mg < 2; mg++)
#pragma unroll
        for (int j = 0; j < 4; j++)
#pragma unroll
            for (int e = 0; e < 4; e++) acc[mg][j][e] = 0.f;
    float csum0 = 0.f, csum1 = 0.f;

    // prologue: stage pair 0 (chunks 0,1) into buffers 0,1
    {
        float4 a0 = *reinterpret_cast<const float4*>(p0);
        float4 b0 = *reinterpret_cast<const float4*>(p1);
        float4 a1 = *reinterpret_cast<const float4*>(p0 + KCH);
        float4 b1 = *reinterpret_cast<const float4*>(p1 + KCH);
        stage_chunk(s_stage[0], a0, b0, lrow, lj, csum0, csum1);
        stage_chunk(s_stage[1], a1, b1, lrow, lj, csum0, csum1);
    }
    __syncthreads();

    for (int t = 0; t < NPAIR; t++) {
        float4 na0, nb0, na1, nb1;
        if (t + 1 < NPAIR) {
            const float* q0 = p0 + (size_t)(2 * t + 2) * KCH;
            const float* q1 = p1 + (size_t)(2 * t + 2) * KCH;
            na0 = *reinterpret_cast<const float4*>(q0);
            nb0 = *reinterpret_cast<const float4*>(q1);
            na1 = *reinterpret_cast<const float4*>(q0 + KCH);
            nb1 = *reinterpret_cast<const float4*>(q1 + KCH);
        }

        // mma over this warp's buffer of the current pair
        const uint32_t* UH = s_stage[2 * (t & 1) + qd];
#pragma unroll
        for (int k8 = 0; k8 < 4; k8++) {
            const int k0 = 8 * k8;
            uint32_t a[2][4];
#pragma unroll
            for (int mg = 0; mg < 2; mg++) {
                int r = rbase + 16 * mg + lq;
                a[mg][0] = UH[r * SMS + k0 + lr];
                a[mg][1] = UH[(r + 8) * SMS + k0 + lr];
                a[mg][2] = UH[r * SMS + k0 + 4 + lr];
                a[mg][3] = UH[(r + 8) * SMS + k0 + 4 + lr];
            }
            uint32_t b[4][2];
#pragma unroll
            for (int j = 0; j < 4; j++) {
                int cn = cbase + 8 * j + lq;
                b[j][0] = UH[cn * SMS + k0 + lr];
                b[j][1] = UH[cn * SMS + k0 + 4 + lr];
            }
#pragma unroll
            for (int mg = 0; mg < 2; mg++)
#pragma unroll
                for (int j = 0; j < 4; j++) mma_tf32(acc[mg][j], a[mg], b[j]);
        }

        // stage next pair into the other buffer pair
        if (t + 1 < NPAIR) {
            const int nb = 2 * ((t + 1) & 1);
            stage_chunk(s_stage[nb],     na0, nb0, lrow, lj, csum0, csum1);
            stage_chunk(s_stage[nb + 1], na1, nb1, lrow, lj, csum0, csum1);
        }
        __syncthreads();
    }

    // ---- epilogue: combine even/odd-chunk partials, write out
    float* Pa = reinterpret_cast<float*>(s_stage[0]);  // 64*65 = 4160 floats, fits
    if (qd == 0) {
#pragma unroll
        for (int mg = 0; mg < 2; mg++) {
            int r = rbase + 16 * mg + lq;
#pragma unroll
            for (int j = 0; j < 4; j++) {
                int cc = cbase + 8 * j + 2 * lr;
                Pa[r * 65 + cc]           = acc[mg][j][0];
                Pa[r * 65 + cc + 1]       = acc[mg][j][1];
                Pa[(r + 8) * 65 + cc]     = acc[mg][j][2];
                Pa[(r + 8) * 65 + cc + 1] = acc[mg][j][3];
            }
        }
    }
    __syncthreads();
    if (qd == 1) {
#pragma unroll
        for (int mg = 0; mg < 2; mg++) {
            int r = rbase + 16 * mg + lq;
#pragma unroll
            for (int j = 0; j < 4; j++) {
                int cc = cbase + 8 * j + 2 * lr;
                Pa[r * 65 + cc]           += acc[mg][j][0];
                Pa[r * 65 + cc + 1]       += acc[mg][j][1];
                Pa[(r + 8) * 65 + cc]     += acc[mg][j][2];
                Pa[(r + 8) * 65 + cc + 1] += acc[mg][j][3];
            }
        }
    }
    // channel sums: reduce within 8-lane groups (same row)
    {
        unsigned full = 0xffffffffu;
#pragma unroll
        for (int o = 4; o > 0; o >>= 1) {
            csum0 += __shfl_xor_sync(full, csum0, o);
            csum1 += __shfl_xor_sync(full, csum1, o);
        }
        if (lj == 0) {
            float* sp = g_sum_part + ((size_t)ks * B_ + bi) * C_;
            sp[lrow] = csum0;
            sp[lrow + 32] = csum1;
        }
    }
    __syncthreads();
    float* gp = g_gram_part + (((size_t)ks * B_ + bi) << 12);
    for (int e = tid; e < 4096; e += 256) {
        int r = e >> 6, cc = e & 63;
        gp[e] = Pa[r * 65 + cc];
    }
}

// ---------------------------------------------------------------------------
// f32x2 helpers for the NS kernel
// ---------------------------------------------------------------------------
__device__ __forceinline__ ull dup2(float v) {
    ull r; asm("mov.b64 %0, {%1, %1};" : "=l"(r) : "f"(v)); return r;
}
__device__ __forceinline__ ull pack2(float x, float y) {
    ull r; asm("mov.b64 %0, {%1, %2};" : "=l"(r) : "f"(x), "f"(y)); return r;
}
__device__ __forceinline__ void ffma2(ull& d, ull a, ull b) {
    asm("fma.rn.f32x2 %0, %1, %2, %0;" : "+l"(d) : "l"(a), "l"(b));
}

template <bool FA, bool FB>
__device__ __forceinline__ void mm64(ull acc[4][2], const float* __restrict__ A,
                                     const float* __restrict__ Bm, int r0, int c0) {
#pragma unroll
    for (int q = 0; q < 4; q++) { acc[q][0] = 0ull; acc[q][1] = 0ull; }
#pragma unroll 4
    for (int k = 0; k < 64; k++) {
        float a[4];
#pragma unroll
        for (int r = 0; r < 4; r++) {
            float v = A[(r0 + r) * 64 + k];
            if (FA) v = ((r0 + r == k) ? 1.5f : 0.0f) - 0.5f * v;
            a[r] = v;
        }
        ull bb[2];
        if (FB) {
            float4 bv = *reinterpret_cast<const float4*>(Bm + k * 64 + c0);
            bv.x = ((k == c0)     ? 1.5f : 0.0f) - 0.5f * bv.x;
            bv.y = ((k == c0 + 1) ? 1.5f : 0.0f) - 0.5f * bv.y;
            bv.z = ((k == c0 + 2) ? 1.5f : 0.0f) - 0.5f * bv.z;
            bv.w = ((k == c0 + 3) ? 1.5f : 0.0f) - 0.5f * bv.w;
            bb[0] = pack2(bv.x, bv.y);
            bb[1] = pack2(bv.z, bv.w);
        } else {
            float4 bv = *reinterpret_cast<const float4*>(Bm + k * 64 + c0);
            bb[0] = pack2(bv.x, bv.y);
            bb[1] = pack2(bv.z, bv.w);
        }
#pragma unroll
        for (int r = 0; r < 4; r++) {
            ull a2 = dup2(a[r]);
            ffma2(acc[r][0], bb[0], a2);
            ffma2(acc[r][1], bb[1], a2);
        }
    }
}

__device__ __forceinline__ void mm_store(const ull acc[4][2], float* __restrict__ Cm,
                                         int r0, int c0) {
#pragma unroll
    for (int r = 0; r < 4; r++) {
        ull* dst = reinterpret_cast<ull*>(Cm + (r0 + r) * 64 + c0);
        dst[0] = acc[r][0]; dst[1] = acc[r][1];
    }
}

// ---------------------------------------------------------------------------
// Kernel 2: reduce partials -> cov -> Newton-Schulz sqrt -> MLP -> gate
// ---------------------------------------------------------------------------
__global__ void __launch_bounds__(256) ns_kernel(const float* __restrict__ gw1,
                                                 const float* __restrict__ gb1,
                                                 const float* __restrict__ gw2,
                                                 const float* __restrict__ gb2) {
    __shared__ __align__(16) float s0[4096];
    __shared__ __align__(16) float s1[4096];
    __shared__ __align__(16) float s2[4096];
    const int bi  = blockIdx.x;
    const int tid = threadIdx.x;
    const int ti = tid >> 4, tj = tid & 15;
    const int r0 = 4 * ti, c0 = 4 * tj;

    {
        const float4* gp = reinterpret_cast<const float4*>(g_gram_part) + bi * 1024;
#pragma unroll
        for (int it = 0; it < 4; it++) {
            int e = it * 256 + tid;
            float4 a4 = make_float4(0.f, 0.f, 0.f, 0.f);
#pragma unroll
            for (int c = 0; c < KSPLIT; c++) {
                float4 v = gp[(size_t)c * (B_ * 1024) + e];
                a4.x += v.x; a4.y += v.y; a4.z += v.z; a4.w += v.w;
            }
            reinterpret_cast<float4*>(s0)[e] = a4;
        }
    }
    if (tid < 64) {
        float s = 0.f;
#pragma unroll
        for (int c = 0; c < KSPLIT; c++) s += g_sum_part[(c * B_ + bi) * C_ + tid];
        s2[tid] = s * (1.0f / M_);
    }
    __syncthreads();
    {
        const float invM = 1.0f / M_;
        for (int e = tid; e < 4096; e += 256) {
            int r = e >> 6, c = e & 63;
            s0[e] = s0[e] * invM - s2[r] * s2[c];
        }
    }
    __syncthreads();
    if (tid < 32) {
        float t = s0[tid * 65] + s0[(tid + 32) * 65];
#pragma unroll
        for (int o = 16; o > 0; o >>= 1) t += __shfl_xor_sync(0xffffffffu, t, o);
        if (tid == 0) s2[64] = t;
    }
    __syncthreads();
    const float normA = s2[64];
    const float rnorm = 1.0f / normA;
    for (int e = tid; e < 4096; e += 256) {
        int r = e >> 6, c = e & 63;
        float a = s0[e] * rnorm;
        s0[e] = a;
        s1[e] = ((r == c) ? 1.5f : 0.0f) - 0.5f * a;
    }
    __syncthreads();
    {
        ull acc[4][2];
        mm64<false, false>(acc, s0, s1, r0, c0);
        mm_store(acc, s2, r0, c0);
    }
    __syncthreads();
    float* Y = s2; float* Z = s1; float* T = s0;
    for (int it = 0; it < 3; it++) {
        ull accT[4][2];
        mm64<true, false>(accT, Z, Y, r0, c0);
        mm_store(accT, T, r0, c0);
        __syncthreads();
        ull accY[4][2], accZ[4][2];
        mm64<false, false>(accY, Y, T, r0, c0);
        mm64<false, false>(accZ, T, Z, r0, c0);
        __syncthreads();
        mm_store(accY, Y, r0, c0);
        mm_store(accZ, Z, r0, c0);
        __syncthreads();
    }
    {
        ull acc[4][2];
        mm64<false, false>(acc, Z, Y, r0, c0);
        mm_store(acc, T, r0, c0);
    }
    __syncthreads();
    {
        ull acc[4][2];
        mm64<false, true>(acc, Y, T, r0, c0);
        mm_store(acc, s1, r0, c0);
    }
    __syncthreads();
    const float scale_s = sqrtf(normA) * (1.0f / 64.0f);
    if (tid < 64) {
        float s = 0.f;
#pragma unroll 8
        for (int i = 0; i < 64; i++) s += s1[i * 64 + tid];
        s0[tid] = s * scale_s;
    }
    __syncthreads();
    if (tid < 8) {
        float h = gb1[tid];
        const float* wr = gw1 + tid * 64;
        for (int j = 0; j < 64; j++) h += s0[j] * wr[j];
        s0[64 + tid] = fmaxf(h, 0.f);
    }
    __syncthreads();
    if (tid < 64) {
        float g = gb2[tid];
        const float* wr = gw2 + tid * 8;
#pragma unroll
        for (int r = 0; r < 8; r++) g += s0[64 + r] * wr[r];
        g_gate[bi * C_ + tid] = 1.0f / (1.0f + expf(-g));
    }
}

// ---------------------------------------------------------------------------
// Kernel 3: out = x * gate[b][c]
// ---------------------------------------------------------------------------
__global__ void __launch_bounds__(256) scale_kernel(const float* __restrict__ x,
                                                    float* __restrict__ out) {
    const int total4 = B_ * C_ * (M_ / 4);
    int i = blockIdx.x * blockDim.x + threadIdx.x;
    if (i >= total4) return;
    int bc = i / (M_ / 4);
    float g = __ldg(&g_gate[bc]);
    float4 v = reinterpret_cast<const float4*>(x)[i];
    v.x *= g; v.y *= g; v.z *= g; v.w *= g;
    reinterpret_cast<float4*>(out)[i] = v;
}

extern "C" void kernel_launch(void* const* d_in, const int* in_sizes, int n_in,
                              void* d_out, int out_size) {
    const float* x  = (const float*)d_in[0];
    const float* w1 = (const float*)d_in[1];
    const float* b1 = (const float*)d_in[2];
    const float* w2 = (const float*)d_in[3];
    const float* b2 = (const float*)d_in[4];
    float* out = (float*)d_out;

    dim3 g1(KSPLIT, B_);
    gram_tc<<<g1, 256>>>(x);
    ns_kernel<<<B_, 256>>>(w1, b1, w2, b2);
    const int total4 = B_ * C_ * (M_ / 4);
    scale_kernel<<<(total4 + 255) / 256, 256>>>(x, out);
}

// round 8
// speedup vs baseline: 1.4451x; 1.4451x over previous
#include <cuda_runtime.h>
#include <cstdint>
#include <math.h>

#define B_ 32
#define C_ 64
#define M_ 9216
#define KSPLIT 12
#define KPC (M_ / KSPLIT)      // 768 k per CTA
#define KCH 32                 // k-chunk width (floats)
#define NCHK (KPC / KCH)       // 24 chunks
#define NPAIR (NCHK / 2)       // 12 pair-iterations
#define SMS 36                 // gram smem row stride
#define NSS 68                 // ns smem row stride (64 + 4: conflict-free mma operand loads)
#define NS_SMEM ((4 * 64 * NSS + 96) * 4)

typedef unsigned long long ull;

// Scratch (no allocs allowed)
__device__ __align__(16) float g_gram_part[KSPLIT * B_ * C_ * C_];
__device__ __align__(16) float g_sum_part[KSPLIT * B_ * C_];
__device__ float g_gate[B_ * C_];

__device__ __forceinline__ uint32_t cvt_tf32(float v) {
    uint32_t r; asm("cvt.rna.tf32.f32 %0, %1;" : "=r"(r) : "f"(v)); return r;
}
__device__ __forceinline__ float rnd_tf32(float v) {
    return __uint_as_float(cvt_tf32(v));
}
__device__ __forceinline__ void mma_tf32(float (&d)[4], const uint32_t a[4], const uint32_t b[2]) {
    asm volatile(
        "mma.sync.aligned.m16n8k8.row.col.f32.tf32.tf32.f32 "
        "{%0,%1,%2,%3}, {%4,%5,%6,%7}, {%8,%9}, {%0,%1,%2,%3};"
        : "+f"(d[0]), "+f"(d[1]), "+f"(d[2]), "+f"(d[3])
        : "r"(a[0]), "r"(a[1]), "r"(a[2]), "r"(a[3]), "r"(b[0]), "r"(b[1]));
}

__device__ __forceinline__ void stage_chunk(uint32_t* dst, float4 v0, float4 v1,
                                            int lrow, int lj, float& cs0, float& cs1) {
    cs0 += v0.x + v0.y + v0.z + v0.w;
    cs1 += v1.x + v1.y + v1.z + v1.w;
    uint4 h0, h1;
    h0.x = cvt_tf32(v0.x); h0.y = cvt_tf32(v0.y); h0.z = cvt_tf32(v0.z); h0.w = cvt_tf32(v0.w);
    h1.x = cvt_tf32(v1.x); h1.y = cvt_tf32(v1.y); h1.z = cvt_tf32(v1.z); h1.w = cvt_tf32(v1.w);
    *reinterpret_cast<uint4*>(dst + lrow * SMS + 4 * lj) = h0;
    *reinterpret_cast<uint4*>(dst + (lrow + 32) * SMS + 4 * lj) = h1;
}

// ---------------------------------------------------------------------------
// Kernel 1: tensor-core Gram, tf32 single-pass (R6 config — best measured).
// ---------------------------------------------------------------------------
__global__ void __launch_bounds__(256, 3) gram_tc(const float* __restrict__ x) {
    __shared__ __align__(16) uint32_t s_stage[4][64 * SMS];  // 36 KB

    const int ks = blockIdx.x, bi = blockIdx.y;
    const int tid = threadIdx.x;
    const int w = tid >> 5, l = tid & 31;
    const int lq = l >> 2, lr = l & 3;
    const int qd = w >> 2, wq = w & 3;
    const int rbase = (wq >> 1) << 5, cbase = (wq & 1) << 5;

    const int lrow = tid >> 3;
    const int lj = tid & 7;

    const float* xb = x + ((size_t)bi * C_) * M_ + (size_t)ks * KPC + 4 * lj;
    const float* p0 = xb + (size_t)lrow * M_;
    const float* p1 = xb + (size_t)(lrow + 32) * M_;

    float acc[2][4][4];
#pragma unroll
    for (int mg = 0; mg < 2; mg++)
#pragma unroll
        for (int j = 0; j < 4; j++)
#pragma unroll
            for (int e = 0; e < 4; e++) acc[mg][j][e] = 0.f;
    float csum0 = 0.f, csum1 = 0.f;

    {
        float4 a0 = *reinterpret_cast<const float4*>(p0);
        float4 b0 = *reinterpret_cast<const float4*>(p1);
        float4 a1 = *reinterpret_cast<const float4*>(p0 + KCH);
        float4 b1 = *reinterpret_cast<const float4*>(p1 + KCH);
        stage_chunk(s_stage[0], a0, b0, lrow, lj, csum0, csum1);
        stage_chunk(s_stage[1], a1, b1, lrow, lj, csum0, csum1);
    }
    __syncthreads();

    for (int t = 0; t < NPAIR; t++) {
        float4 na0, nb0, na1, nb1;
        if (t + 1 < NPAIR) {
            const float* q0 = p0 + (size_t)(2 * t + 2) * KCH;
            const float* q1 = p1 + (size_t)(2 * t + 2) * KCH;
            na0 = *reinterpret_cast<const float4*>(q0);
            nb0 = *reinterpret_cast<const float4*>(q1);
            na1 = *reinterpret_cast<const float4*>(q0 + KCH);
            nb1 = *reinterpret_cast<const float4*>(q1 + KCH);
        }

        const uint32_t* UH = s_stage[2 * (t & 1) + qd];
#pragma unroll
        for (int k8 = 0; k8 < 4; k8++) {
            const int k0 = 8 * k8;
            uint32_t a[2][4];
#pragma unroll
            for (int mg = 0; mg < 2; mg++) {
                int r = rbase + 16 * mg + lq;
                a[mg][0] = UH[r * SMS + k0 + lr];
                a[mg][1] = UH[(r + 8) * SMS + k0 + lr];
                a[mg][2] = UH[r * SMS + k0 + 4 + lr];
                a[mg][3] = UH[(r + 8) * SMS + k0 + 4 + lr];
            }
            uint32_t b[4][2];
#pragma unroll
            for (int j = 0; j < 4; j++) {
                int cn = cbase + 8 * j + lq;
                b[j][0] = UH[cn * SMS + k0 + lr];
                b[j][1] = UH[cn * SMS + k0 + 4 + lr];
            }
#pragma unroll
            for (int mg = 0; mg < 2; mg++)
#pragma unroll
                for (int j = 0; j < 4; j++) mma_tf32(acc[mg][j], a[mg], b[j]);
        }

        if (t + 1 < NPAIR) {
            const int nb = 2 * ((t + 1) & 1);
            stage_chunk(s_stage[nb],     na0, nb0, lrow, lj, csum0, csum1);
            stage_chunk(s_stage[nb + 1], na1, nb1, lrow, lj, csum0, csum1);
        }
        __syncthreads();
    }

    float* Pa = reinterpret_cast<float*>(s_stage[0]);
    if (qd == 0) {
#pragma unroll
        for (int mg = 0; mg < 2; mg++) {
            int r = rbase + 16 * mg + lq;
#pragma unroll
            for (int j = 0; j < 4; j++) {
                int cc = cbase + 8 * j + 2 * lr;
                Pa[r * 65 + cc]           = acc[mg][j][0];
                Pa[r * 65 + cc + 1]       = acc[mg][j][1];
                Pa[(r + 8) * 65 + cc]     = acc[mg][j][2];
                Pa[(r + 8) * 65 + cc + 1] = acc[mg][j][3];
            }
        }
    }
    __syncthreads();
    if (qd == 1) {
#pragma unroll
        for (int mg = 0; mg < 2; mg++) {
            int r = rbase + 16 * mg + lq;
#pragma unroll
            for (int j = 0; j < 4; j++) {
                int cc = cbase + 8 * j + 2 * lr;
                Pa[r * 65 + cc]           += acc[mg][j][0];
                Pa[r * 65 + cc + 1]       += acc[mg][j][1];
                Pa[(r + 8) * 65 + cc]     += acc[mg][j][2];
                Pa[(r + 8) * 65 + cc + 1] += acc[mg][j][3];
            }
        }
    }
    {
        unsigned full = 0xffffffffu;
#pragma unroll
        for (int o = 4; o > 0; o >>= 1) {
            csum0 += __shfl_xor_sync(full, csum0, o);
            csum1 += __shfl_xor_sync(full, csum1, o);
        }
        if (lj == 0) {
            float* sp = g_sum_part + ((size_t)ks * B_ + bi) * C_;
            sp[lrow] = csum0;
            sp[lrow + 32] = csum1;
        }
    }
    __syncthreads();
    float* gp = g_gram_part + (((size_t)ks * B_ + bi) << 12);
    for (int e = tid; e < 4096; e += 256) {
        int r = e >> 6, cc = e & 63;
        gp[e] = Pa[r * 65 + cc];
    }
}

// ---------------------------------------------------------------------------
// NS matmul on tensor cores: C = A @ B over 64x64, warp w owns a 32x16 tile.
// A, B are row-major [64][NSS] fp32 whose values are tf32-rounded.
// ---------------------------------------------------------------------------
__device__ __forceinline__ void mm64t(float acc[2][2][4],
                                      const float* __restrict__ A,
                                      const float* __restrict__ B,
                                      int m0, int n0, int lq, int lr) {
    const uint32_t* UA = reinterpret_cast<const uint32_t*>(A);
    const uint32_t* UB = reinterpret_cast<const uint32_t*>(B);
#pragma unroll
    for (int mg = 0; mg < 2; mg++)
#pragma unroll
        for (int ng = 0; ng < 2; ng++)
#pragma unroll
            for (int e = 0; e < 4; e++) acc[mg][ng][e] = 0.f;
#pragma unroll
    for (int k8 = 0; k8 < 8; k8++) {
        const int k0 = 8 * k8;
        uint32_t a[2][4], b[2][2];
#pragma unroll
        for (int mg = 0; mg < 2; mg++) {
            int r = m0 + 16 * mg + lq;
            a[mg][0] = UA[r * NSS + k0 + lr];
            a[mg][1] = UA[(r + 8) * NSS + k0 + lr];
            a[mg][2] = UA[r * NSS + k0 + 4 + lr];
            a[mg][3] = UA[(r + 8) * NSS + k0 + 4 + lr];
        }
#pragma unroll
        for (int ng = 0; ng < 2; ng++) {
            int cn = n0 + 8 * ng + lq;
            b[ng][0] = UB[(k0 + lr) * NSS + cn];
            b[ng][1] = UB[(k0 + 4 + lr) * NSS + cn];
        }
#pragma unroll
        for (int mg = 0; mg < 2; mg++)
#pragma unroll
            for (int ng = 0; ng < 2; ng++) mma_tf32(acc[mg][ng], a[mg], b[ng]);
    }
}

// store frags (tf32-rounded) to row-major [64][NSS]
__device__ __forceinline__ void frag_store(const float acc[2][2][4], float* __restrict__ D,
                                           int m0, int n0, int lq, int lr) {
#pragma unroll
    for (int mg = 0; mg < 2; mg++)
#pragma unroll
        for (int ng = 0; ng < 2; ng++) {
            int r = m0 + 16 * mg + lq;
            int cc = n0 + 8 * ng + 2 * lr;
            D[r * NSS + cc]           = rnd_tf32(acc[mg][ng][0]);
            D[r * NSS + cc + 1]       = rnd_tf32(acc[mg][ng][1]);
            D[(r + 8) * NSS + cc]     = rnd_tf32(acc[mg][ng][2]);
            D[(r + 8) * NSS + cc + 1] = rnd_tf32(acc[mg][ng][3]);
        }
}

// D = rnd(1.5*Y - 0.5*acc) at frag coords
__device__ __forceinline__ void frag_store_zy(const float acc[2][2][4],
                                              const float* __restrict__ Y,
                                              float* __restrict__ D,
                                              int m0, int n0, int lq, int lr) {
#pragma unroll
    for (int mg = 0; mg < 2; mg++)
#pragma unroll
        for (int ng = 0; ng < 2; ng++) {
            int r = m0 + 16 * mg + lq;
            int cc = n0 + 8 * ng + 2 * lr;
            D[r * NSS + cc]           = rnd_tf32(1.5f * Y[r * NSS + cc]           - 0.5f * acc[mg][ng][0]);
            D[r * NSS + cc + 1]       = rnd_tf32(1.5f * Y[r * NSS + cc + 1]       - 0.5f * acc[mg][ng][1]);
            D[(r + 8) * NSS + cc]     = rnd_tf32(1.5f * Y[(r + 8) * NSS + cc]     - 0.5f * acc[mg][ng][2]);
            D[(r + 8) * NSS + cc + 1] = rnd_tf32(1.5f * Y[(r + 8) * NSS + cc + 1] - 0.5f * acc[mg][ng][3]);
        }
}

// ---------------------------------------------------------------------------
// Kernel 2: reduce partials -> cov -> Newton-Schulz (tensor-core) -> MLP
// ---------------------------------------------------------------------------
__global__ void __launch_bounds__(256) ns_kernel(const float* __restrict__ gw1,
                                                 const float* __restrict__ gb1,
                                                 const float* __restrict__ gw2,
                                                 const float* __restrict__ gb2) {
    extern __shared__ __align__(16) float sm[];
    float* bufA = sm;                    // cov / F scratch
    float* bufY = sm + 64 * NSS;
    float* bufZ = sm + 2 * 64 * NSS;
    float* bufT = sm + 3 * 64 * NSS;     // ZY / W
    float* aux  = sm + 4 * 64 * NSS;     // [0..63] mu / s, [64] trace, [72..79] h

    const int bi  = blockIdx.x;
    const int tid = threadIdx.x;
    const int w = tid >> 5, l = tid & 31;
    const int lq = l >> 2, lr = l & 3;
    const int m0 = (w & 1) * 32, n0 = (w >> 1) * 16;

    // 1) reduce partial grams -> raw G into bufA (row stride NSS)
    {
        const float4* gp = reinterpret_cast<const float4*>(g_gram_part) + bi * 1024;
#pragma unroll
        for (int it = 0; it < 4; it++) {
            int e4 = it * 256 + tid;           // float4 index: row = e4>>4, col4 = e4&15
            float4 a4 = make_float4(0.f, 0.f, 0.f, 0.f);
#pragma unroll
            for (int c = 0; c < KSPLIT; c++) {
                float4 v = gp[(size_t)c * (B_ * 1024) + e4];
                a4.x += v.x; a4.y += v.y; a4.z += v.z; a4.w += v.w;
            }
            int r = e4 >> 4, c4 = e4 & 15;
            *reinterpret_cast<float4*>(&bufA[r * NSS + 4 * c4]) = a4;
        }
    }
    if (tid < 64) {
        float s = 0.f;
#pragma unroll
        for (int c = 0; c < KSPLIT; c++) s += g_sum_part[(c * B_ + bi) * C_ + tid];
        aux[tid] = s * (1.0f / M_);
    }
    __syncthreads();
    // 2) cov = G/M - mu mu^T
    {
        const float invM = 1.0f / M_;
        for (int e = tid; e < 4096; e += 256) {
            int r = e >> 6, c = e & 63;
            bufA[r * NSS + c] = bufA[r * NSS + c] * invM - aux[r] * aux[c];
        }
    }
    __syncthreads();
    // 3) trace
    if (tid < 32) {
        float t = bufA[tid * (NSS + 1)] + bufA[(tid + 32) * (NSS + 1)];
#pragma unroll
        for (int o = 16; o > 0; o >>= 1) t += __shfl_xor_sync(0xffffffffu, t, o);
        if (tid == 0) aux[64] = t;
    }
    __syncthreads();
    const float normA = aux[64];
    const float rnorm = 1.0f / normA;
    // 4) A = rnd(cov*rnorm); Z0 = rnd(1.5I - 0.5A)
    for (int e = tid; e < 4096; e += 256) {
        int r = e >> 6, c = e & 63;
        float a = rnd_tf32(bufA[r * NSS + c] * rnorm);
        bufA[r * NSS + c] = a;
        bufZ[r * NSS + c] = rnd_tf32(((r == c) ? 1.5f : 0.0f) - 0.5f * a);
    }
    __syncthreads();
    // 5) Y = A @ Z0
    {
        float acc[2][2][4];
        mm64t(acc, bufA, bufZ, m0, n0, lq, lr);
        frag_store(acc, bufY, m0, n0, lq, lr);
    }
    __syncthreads();
    // 6) three NS iterations
    for (int it = 0; it < 3; it++) {
        {
            float acc[2][2][4];
            mm64t(acc, bufZ, bufY, m0, n0, lq, lr);          // U = Z@Y
            frag_store_zy(acc, bufY, bufT, m0, n0, lq, lr);  // T = rnd(1.5Y - 0.5U)
        }
        __syncthreads();
        {
            float accY[2][2][4], accZ[2][2][4];
            mm64t(accY, bufY, bufT, m0, n0, lq, lr);         // Y' = Y@T
            mm64t(accZ, bufT, bufZ, m0, n0, lq, lr);         // Z' = T@Z
            __syncthreads();                                 // all reads done
            frag_store(accY, bufY, m0, n0, lq, lr);
            frag_store(accZ, bufZ, m0, n0, lq, lr);
        }
        __syncthreads();
    }
    // 7) W = Z@Y -> bufT
    {
        float acc[2][2][4];
        mm64t(acc, bufZ, bufY, m0, n0, lq, lr);
        frag_store(acc, bufT, m0, n0, lq, lr);
    }
    __syncthreads();
    // 8) F = 1.5Y - 0.5*(Y@W) -> bufA (no rounding needed but harmless)
    {
        float acc[2][2][4];
        mm64t(acc, bufY, bufT, m0, n0, lq, lr);
        __syncthreads();
        frag_store_zy(acc, bufY, bufA, m0, n0, lq, lr);
    }
    __syncthreads();
    // 9) s_j = sqrt(normA)/64 * colsum(F)
    const float scale_s = sqrtf(normA) * (1.0f / 64.0f);
    if (tid < 64) {
        float s = 0.f;
#pragma unroll 8
        for (int i = 0; i < 64; i++) s += bufA[i * NSS + tid];
        aux[tid] = s * scale_s;
    }
    __syncthreads();
    // 10) MLP
    if (tid < 8) {
        float h = gb1[tid];
        const float* wr = gw1 + tid * 64;
        for (int j = 0; j < 64; j++) h += aux[j] * wr[j];
        aux[72 + tid] = fmaxf(h, 0.f);
    }
    __syncthreads();
    if (tid < 64) {
        float g = gb2[tid];
        const float* wr = gw2 + tid * 8;
#pragma unroll
        for (int r = 0; r < 8; r++) g += aux[72 + r] * wr[r];
        g_gate[bi * C_ + tid] = 1.0f / (1.0f + expf(-g));
    }
}

// ---------------------------------------------------------------------------
// Kernel 3: out = x * gate[b][c]
// ---------------------------------------------------------------------------
__global__ void __launch_bounds__(256) scale_kernel(const float* __restrict__ x,
                                                    float* __restrict__ out) {
    const int total4 = B_ * C_ * (M_ / 4);
    int i = blockIdx.x * blockDim.x + threadIdx.x;
    if (i >= total4) return;
    int bc = i / (M_ / 4);
    float g = __ldg(&g_gate[bc]);
    float4 v = reinterpret_cast<const float4*>(x)[i];
    v.x *= g; v.y *= g; v.z *= g; v.w *= g;
    reinterpret_cast<float4*>(out)[i] = v;
}

extern "C" void kernel_launch(void* const* d_in, const int* in_sizes, int n_in,
                              void* d_out, int out_size) {
    const float* x  = (const float*)d_in[0];
    const float* w1 = (const float*)d_in[1];
    const float* b1 = (const float*)d_in[2];
    const float* w2 = (const float*)d_in[3];
    const float* b2 = (const float*)d_in[4];
    float* out = (float*)d_out;

    static int ns_attr_set = 0;
    if (!ns_attr_set) {
        cudaFuncSetAttribute(ns_kernel, cudaFuncAttributeMaxDynamicSharedMemorySize, NS_SMEM);
        ns_attr_set = 1;
    }

    dim3 g1(KSPLIT, B_);
    gram_tc<<<g1, 256>>>(x);
    ns_kernel<<<B_, 256, NS_SMEM>>>(w1, b1, w2, b2);
    const int total4 = B_ * C_ * (M_ / 4);
    scale_kernel<<<(total4 + 255) / 256, 256>>>(x, out);
}